// round 7
// baseline (speedup 1.0000x reference)
#include <cuda_runtime.h>

// cost = where(0<=v<=1, A*exp(B*(1+v)) + C, OOB_COST), v = X[i*8+7]
// A=0.01, B=4.81, C=0.0, OOB=3.0
// Streaming kernel at HBM roofline (87.5% DRAM @ R6). Lane-major mapping:
// each LDG's 32 lanes hit 32 consecutive rows = 8 x 128B lines; each STG is
// one coalesced 128B line. 16 rows/thread: MLP=16 front-batch, half the
// issue overhead of R6's 8.

__device__ __forceinline__ float penalize(float v) {
    float c = 0.01f * __expf(4.81f * (1.0f + v));
    return (v >= 0.0f && v <= 1.0f) ? c : 3.0f;
}

#define ROWS_PER_THREAD 16

__global__ __launch_bounds__(256)
void penalizer_kernel(const float* __restrict__ X,
                      float* __restrict__ out,
                      int n) {
    const int ROWS_PER_BLOCK = 256 * ROWS_PER_THREAD;
    int base = blockIdx.x * ROWS_PER_BLOCK + threadIdx.x;

    if (base + 256 * (ROWS_PER_THREAD - 1) < n) {
        float v[ROWS_PER_THREAD];
#pragma unroll
        for (int j = 0; j < ROWS_PER_THREAD; ++j)
            v[j] = __ldcs(X + (size_t)(base + 256 * j) * 8 + 7);

#pragma unroll
        for (int j = 0; j < ROWS_PER_THREAD; ++j)
            __stcs(out + base + 256 * j, penalize(v[j]));
    } else {
        // Tail block (not taken when n % (256*ROWS_PER_THREAD) == 0)
#pragma unroll
        for (int j = 0; j < ROWS_PER_THREAD; ++j) {
            int r = base + 256 * j;
            if (r < n) {
                float vv = __ldcs(X + (size_t)r * 8 + 7);
                out[r] = penalize(vv);
            }
        }
    }
}

extern "C" void kernel_launch(void* const* d_in, const int* in_sizes, int n_in,
                              void* d_out, int out_size) {
    const float* X = (const float*)d_in[0];
    float* out = (float*)d_out;
    int n = out_size;  // one output per row; in_sizes[0] == n*8

    int threads = 256;
    int rows_per_block = threads * ROWS_PER_THREAD;
    int blocks = (n + rows_per_block - 1) / rows_per_block;  // 4096 for n=16.7M
    penalizer_kernel<<<blocks, threads>>>(X, out, n);
}

// round 8
// speedup vs baseline: 1.0103x; 1.0103x over previous
#include <cuda_runtime.h>

// cost = where(0<=v<=1, A*exp(B*(1+v)) + C, OOB_COST), v = X[i*8+7]
// A=0.01, B=4.81, C=0.0, OOB=3.0
//
// CONVERGED streaming kernel at the achieved-HBM roofline:
//   - traffic floor: 512MB read (stride-8 fp32 -> one 32B sector per row,
//     every sector needed) + 64MB write = 576MB irreducible
//   - lane-major mapping: each LDG's 32 lanes hit 32 consecutive rows
//     = 8 x 128B lines/warp (minimal L1tex wavefronts); each STG is one
//     fully-coalesced 128B line
//   - 8 rows/thread front-batched MLP=8; __ldcs/__stcs cold-stream hints
//   - oversubscribed grid (8192 CTAs) for retire-backfill
// Measured: 84.0us kernel / 86.5us wall, DRAM=87.5%, 6.93 TB/s.

__device__ __forceinline__ float penalize(float v) {
    float c = 0.01f * __expf(4.81f * (1.0f + v));
    return (v >= 0.0f && v <= 1.0f) ? c : 3.0f;
}

__global__ __launch_bounds__(256)
void penalizer_kernel(const float* __restrict__ X,
                      float* __restrict__ out,
                      int n) {
    const int ROWS_PER_BLOCK = 256 * 8;
    int base = blockIdx.x * ROWS_PER_BLOCK + threadIdx.x;

    if (base + 256 * 7 < n) {
        float v[8];
#pragma unroll
        for (int j = 0; j < 8; ++j)
            v[j] = __ldcs(X + (size_t)(base + 256 * j) * 8 + 7);

#pragma unroll
        for (int j = 0; j < 8; ++j)
            __stcs(out + base + 256 * j, penalize(v[j]));
    } else {
        // Tail block (not taken when n % 2048 == 0)
#pragma unroll
        for (int j = 0; j < 8; ++j) {
            int r = base + 256 * j;
            if (r < n) {
                float vv = __ldcs(X + (size_t)r * 8 + 7);
                out[r] = penalize(vv);
            }
        }
    }
}

extern "C" void kernel_launch(void* const* d_in, const int* in_sizes, int n_in,
                              void* d_out, int out_size) {
    const float* X = (const float*)d_in[0];
    float* out = (float*)d_out;
    int n = out_size;  // one output per row; in_sizes[0] == n*8

    int threads = 256;
    int rows_per_block = threads * 8;
    int blocks = (n + rows_per_block - 1) / rows_per_block;  // 8192 for n=16.7M
    penalizer_kernel<<<blocks, threads>>>(X, out, n);
}

// round 9
// speedup vs baseline: 1.0192x; 1.0089x over previous
#include <cuda_runtime.h>

// cost = where(0<=v<=1, A*exp(B*(1+v)) + C, OOB_COST), v = X[i*8+7]
// A=0.01, B=4.81, C=0.0, OOB=3.0
//
// CONVERGED streaming kernel at the achieved-HBM roofline:
//   - traffic floor: 512MB read (stride-8 fp32 -> one 32B sector per row,
//     every sector needed) + 64MB write = 576MB irreducible
//   - lane-major mapping: each LDG's 32 lanes hit 32 consecutive rows
//     = 8 x 128B lines/warp (minimal L1tex wavefronts); each STG is one
//     fully-coalesced 128B line
//   - 8 rows/thread front-batched MLP=8; __ldcs/__stcs cold-stream hints
//   - oversubscribed grid (8192 CTAs) for retire-backfill
// Measured: 83.6us kernel / 87.4us wall, DRAM=88.0%, 6.97 TB/s (87% of spec).

__device__ __forceinline__ float penalize(float v) {
    float c = 0.01f * __expf(4.81f * (1.0f + v));
    return (v >= 0.0f && v <= 1.0f) ? c : 3.0f;
}

__global__ __launch_bounds__(256)
void penalizer_kernel(const float* __restrict__ X,
                      float* __restrict__ out,
                      int n) {
    const int ROWS_PER_BLOCK = 256 * 8;
    int base = blockIdx.x * ROWS_PER_BLOCK + threadIdx.x;

    if (base + 256 * 7 < n) {
        float v[8];
#pragma unroll
        for (int j = 0; j < 8; ++j)
            v[j] = __ldcs(X + (size_t)(base + 256 * j) * 8 + 7);

#pragma unroll
        for (int j = 0; j < 8; ++j)
            __stcs(out + base + 256 * j, penalize(v[j]));
    } else {
        // Tail block (not taken when n % 2048 == 0)
#pragma unroll
        for (int j = 0; j < 8; ++j) {
            int r = base + 256 * j;
            if (r < n) {
                float vv = __ldcs(X + (size_t)r * 8 + 7);
                out[r] = penalize(vv);
            }
        }
    }
}

extern "C" void kernel_launch(void* const* d_in, const int* in_sizes, int n_in,
                              void* d_out, int out_size) {
    const float* X = (const float*)d_in[0];
    float* out = (float*)d_out;
    int n = out_size;  // one output per row; in_sizes[0] == n*8

    int threads = 256;
    int rows_per_block = threads * 8;
    int blocks = (n + rows_per_block - 1) / rows_per_block;  // 8192 for n=16.7M
    penalizer_kernel<<<blocks, threads>>>(X, out, n);
}